// round 3
// baseline (speedup 1.0000x reference)
#include <cuda_runtime.h>
#include <math.h>

#define NN 50000
#define EE 800000
#define TT 2

// ---------------- scratch (static device globals; no allocation) ----------------
__device__ float  g_fh[(size_t)TT * NN * 128];   // projected features per type
__device__ float4 g_el[TT * NN];                 // per-node left attn logits (4 heads)
__device__ float4 g_er[TT * NN];                 // per-node right attn logits
__device__ int    g_deg[TT * NN];
__device__ int    g_start[TT * NN];
__device__ int    g_cnt[TT * NN];
__device__ int    g_col[TT * EE];                // CSR-by-dst: src ids

// ---------------- helpers ----------------
__device__ __forceinline__ float lrelu(float x) { return x > 0.f ? x : 0.2f * x; }

__device__ __forceinline__ float wsum(float v) {
#pragma unroll
    for (int o = 16; o > 0; o >>= 1) v += __shfl_xor_sync(0xffffffffu, v, o);
    return v;
}
__device__ __forceinline__ float wmax(float v) {
#pragma unroll
    for (int o = 16; o > 0; o >>= 1) v = fmaxf(v, __shfl_xor_sync(0xffffffffu, v, o));
    return v;
}
__device__ __forceinline__ unsigned tf32u(float x) {
    unsigned u; asm("cvt.rna.tf32.f32 %0, %1;" : "=r"(u) : "f"(x)); return u;
}
__device__ __forceinline__ float tf32f(float x) { return __uint_as_float(tf32u(x)); }

// permute k within each 8-group so (k, k+4) become adjacent: [0,4,1,5,2,6,3,7]
__device__ __forceinline__ int kperm(int k) {
    return (k & ~7) | ((k & 3) << 1) | ((k >> 2) & 1);
}

// ---------------- kernels ----------------
__global__ void init_kernel() {
    int i = blockIdx.x * blockDim.x + threadIdx.x;
    if (i < TT * NN) { g_deg[i] = 0; g_cnt[i] = 0; }
}

// fh[t] = feature @ W[t] via tf32 mma.sync m16n8k8.
// Block 256 thr (8 warps). Block tile 128(M) x 128(N), K=128 in chunks of 32.
// Warp w owns rows [w*16, w*16+16), all 128 cols: 16 n-tiles of m16n8.
#define BS_STRIDE 132
#define AS_STRIDE 36
__global__ void gemm_tf32_kernel(const float* __restrict__ feat, const float* __restrict__ W) {
    extern __shared__ float sm[];
    float* Bs = sm;                       // [n=128][k=132 padded], k permuted, tf32 bits
    float* As = sm + 128 * BS_STRIDE;     // [row=128][k=36 padded], k permuted, tf32 bits

    const int t    = blockIdx.y;
    const int m0   = blockIdx.x * 128;
    const int tid  = threadIdx.x;
    const int lane = tid & 31;
    const int wr   = (tid >> 5) * 16;     // warp row base
    const int q    = lane >> 2;           // 0..7
    const int c2   = (lane & 3) * 2;      // 0,2,4,6 (permuted-k offset)

    // load W[t] (128x128, row k, col n), transpose+permute into Bs[n][pk]
    const float* Wt = W + t * 16384;
#pragma unroll
    for (int i = 0; i < 64; i++) {
        int e = tid + i * 256;
        int k = e >> 7, n = e & 127;
        Bs[n * BS_STRIDE + kperm(k)] = tf32f(Wt[e]);
    }

    float c[16][4];
#pragma unroll
    for (int j = 0; j < 16; j++)
#pragma unroll
        for (int v = 0; v < 4; v++) c[j][v] = 0.f;

    for (int kt = 0; kt < 128; kt += 32) {
        // load A tile 128x32 (tf32, permuted-k)
#pragma unroll
        for (int i = 0; i < 4; i++) {
            int qq  = tid + i * 256;          // 0..1023
            int row = qq >> 3;
            int kc  = (qq & 7) * 4;
            int gr  = m0 + row;
            float4 v = (gr < NN) ? *(const float4*)(feat + (size_t)gr * 128 + kt + kc)
                                 : make_float4(0.f, 0.f, 0.f, 0.f);
            As[row * AS_STRIDE + kperm(kc + 0)] = tf32f(v.x);
            As[row * AS_STRIDE + kperm(kc + 1)] = tf32f(v.y);
            As[row * AS_STRIDE + kperm(kc + 2)] = tf32f(v.z);
            As[row * AS_STRIDE + kperm(kc + 3)] = tf32f(v.w);
        }
        __syncthreads();

#pragma unroll
        for (int kk = 0; kk < 32; kk += 8) {
            float2 fa0 = *(const float2*)&As[(wr + q)     * AS_STRIDE + kk + c2];
            float2 fa1 = *(const float2*)&As[(wr + q + 8) * AS_STRIDE + kk + c2];
            unsigned a0 = __float_as_uint(fa0.x), a2 = __float_as_uint(fa0.y);
            unsigned a1 = __float_as_uint(fa1.x), a3 = __float_as_uint(fa1.y);
#pragma unroll
            for (int j = 0; j < 16; j++) {
                // NOTE: + kt — Bs holds the full K=128; select this k-chunk
                float2 fb = *(const float2*)&Bs[(j * 8 + q) * BS_STRIDE + kt + kk + c2];
                unsigned b0 = __float_as_uint(fb.x), b1 = __float_as_uint(fb.y);
                asm volatile(
                    "mma.sync.aligned.m16n8k8.row.col.f32.tf32.tf32.f32 "
                    "{%0,%1,%2,%3},{%4,%5,%6,%7},{%8,%9},{%0,%1,%2,%3};"
                    : "+f"(c[j][0]), "+f"(c[j][1]), "+f"(c[j][2]), "+f"(c[j][3])
                    : "r"(a0), "r"(a1), "r"(a2), "r"(a3), "r"(b0), "r"(b1));
            }
        }
        __syncthreads();
    }

    // epilogue: c0,c1 -> (row wr+q, cols j*8+c2, +1); c2,c3 -> row +8
    int r0 = m0 + wr + q;
    int r1 = r0 + 8;
    float* fhT = g_fh + (size_t)t * NN * 128;
#pragma unroll
    for (int j = 0; j < 16; j++) {
        int col = j * 8 + c2;
        if (r0 < NN) *(float2*)(fhT + (size_t)r0 * 128 + col) = make_float2(c[j][0], c[j][1]);
        if (r1 < NN) *(float2*)(fhT + (size_t)r1 * 128 + col) = make_float2(c[j][2], c[j][3]);
    }
}

// el/er = head-wise dot(fh, attn_l/r). One warp per node.
__global__ void elr_kernel(const float* __restrict__ al, const float* __restrict__ ar) {
    int lane = threadIdx.x & 31;
    int n    = blockIdx.x * (blockDim.x >> 5) + (threadIdx.x >> 5);
    int t    = blockIdx.y;
    if (n >= NN) return;
    const float* f = g_fh + ((size_t)t * NN + n) * 128 + lane;
    float pl[4], pr[4];
#pragma unroll
    for (int k = 0; k < 4; k++) {
        float v = f[32 * k];
        pl[k] = v * al[t * 128 + lane + 32 * k];
        pr[k] = v * ar[t * 128 + lane + 32 * k];
    }
#pragma unroll
    for (int k = 0; k < 4; k++) { pl[k] = wsum(pl[k]); pr[k] = wsum(pr[k]); }
    if (lane == 0) {
        g_el[t * NN + n] = make_float4(pl[0], pl[1], pl[2], pl[3]);
        g_er[t * NN + n] = make_float4(pr[0], pr[1], pr[2], pr[3]);
    }
}

__global__ void hist_kernel(const int* __restrict__ dst) {
    int i = blockIdx.x * blockDim.x + threadIdx.x;
    int t = blockIdx.y;
    if (i < EE) atomicAdd(&g_deg[t * NN + dst[t * EE + i]], 1);
}

// exclusive scan of degrees -> start offsets. One block per type.
__global__ void scan_kernel() {
    __shared__ int sm[1024];
    int t = blockIdx.x;
    const int* deg = &g_deg[t * NN];
    int* st = &g_start[t * NN];
    int tid = threadIdx.x;
    const int C = (NN + 1023) / 1024;
    int base = tid * C;
    int s = 0;
    for (int i = 0; i < C; i++) { int idx = base + i; if (idx < NN) s += deg[idx]; }
    sm[tid] = s;
    __syncthreads();
    for (int off = 1; off < 1024; off <<= 1) {
        int v = (tid >= off) ? sm[tid - off] : 0;
        __syncthreads();
        sm[tid] += v;
        __syncthreads();
    }
    int run = sm[tid] - s;
    for (int i = 0; i < C; i++) {
        int idx = base + i;
        if (idx < NN) { st[idx] = run; run += deg[idx]; }
    }
}

__global__ void scatter_kernel(const int* __restrict__ src, const int* __restrict__ dst) {
    int i = blockIdx.x * blockDim.x + threadIdx.x;
    int t = blockIdx.y;
    if (i >= EE) return;
    int d = dst[t * EE + i];
    int p = g_start[t * NN + d] + atomicAdd(&g_cnt[t * NN + d], 1);
    g_col[t * EE + p] = src[t * EE + i];
}

// fused attention + aggregation + bias + LayerNorm + ELU.
// One block (128 thr) per (node, type). Thread tid owns output dim tid (head = tid>>5).
#define CH 128
__global__ void attn_kernel(const float* __restrict__ bias, const float* __restrict__ lnw,
                            const float* __restrict__ lnb, float* __restrict__ out) {
    __shared__ int   s_src[CH];
    __shared__ float s_e[4 * CH];        // logits -> weights (per head)
    __shared__ float s_mrun[4], s_srun[4], s_r[4];
    __shared__ float s_red[4];

    const float NEG_INF = __int_as_float(0xff800000);
    int tid  = threadIdx.x;
    int lane = tid & 31;
    int wid  = tid >> 5;                 // also this thread's head
    int n    = blockIdx.x;
    int t    = blockIdx.y;
    int base = t * NN + n;

    if (tid < 4) { s_mrun[tid] = NEG_INF; s_srun[tid] = 0.f; }

    float4 er4 = g_er[base];
    int beg = g_start[base];
    int deg = g_deg[base];
    const float* fhT  = g_fh + (size_t)t * NN * 128;
    const int*   colT = g_col + t * EE;

    float acc = 0.f;
    __syncthreads();

    for (int pos = 0; pos < deg; pos += CH) {
        int cnt = min(CH, deg - pos);
        if (tid < cnt) {
            int s = colT[beg + pos + tid];
            s_src[tid] = s;
            float4 el4 = g_el[t * NN + s];
            s_e[0 * CH + tid] = lrelu(el4.x + er4.x);
            s_e[1 * CH + tid] = lrelu(el4.y + er4.y);
            s_e[2 * CH + tid] = lrelu(el4.z + er4.z);
            s_e[3 * CH + tid] = lrelu(el4.w + er4.w);
        }
        __syncthreads();
        // warp `wid` handles head `wid`: chunk max, exp in place, chunk sum
        {
            float mx = NEG_INF;
            for (int i = lane; i < cnt; i += 32) mx = fmaxf(mx, s_e[wid * CH + i]);
            mx = wmax(mx);
            float mnew = fmaxf(s_mrun[wid], mx);
            float sum = 0.f;
            for (int i = lane; i < cnt; i += 32) {
                float w = __expf(s_e[wid * CH + i] - mnew);
                s_e[wid * CH + i] = w;
                sum += w;
            }
            sum = wsum(sum);
            if (lane == 0) {
                float r = __expf(s_mrun[wid] - mnew);
                s_r[wid] = r;
                s_srun[wid] = s_srun[wid] * r + sum;
                s_mrun[wid] = mnew;
            }
        }
        __syncthreads();
        // aggregate: thread owns dim `tid`, streams coalesced gathers
        acc *= s_r[wid];
        const float* wrow = &s_e[wid * CH];
        int e = 0;
        for (; e + 8 <= cnt; e += 8) {
            int i0 = s_src[e],     i1 = s_src[e + 1], i2 = s_src[e + 2], i3 = s_src[e + 3];
            int i4 = s_src[e + 4], i5 = s_src[e + 5], i6 = s_src[e + 6], i7 = s_src[e + 7];
            float v0 = fhT[(size_t)i0 * 128 + tid];
            float v1 = fhT[(size_t)i1 * 128 + tid];
            float v2 = fhT[(size_t)i2 * 128 + tid];
            float v3 = fhT[(size_t)i3 * 128 + tid];
            float v4 = fhT[(size_t)i4 * 128 + tid];
            float v5 = fhT[(size_t)i5 * 128 + tid];
            float v6 = fhT[(size_t)i6 * 128 + tid];
            float v7 = fhT[(size_t)i7 * 128 + tid];
            acc = fmaf(wrow[e],     v0, acc);
            acc = fmaf(wrow[e + 1], v1, acc);
            acc = fmaf(wrow[e + 2], v2, acc);
            acc = fmaf(wrow[e + 3], v3, acc);
            acc = fmaf(wrow[e + 4], v4, acc);
            acc = fmaf(wrow[e + 5], v5, acc);
            acc = fmaf(wrow[e + 6], v6, acc);
            acc = fmaf(wrow[e + 7], v7, acc);
        }
        for (; e < cnt; e++)
            acc = fmaf(wrow[e], fhT[(size_t)s_src[e] * 128 + tid], acc);
        __syncthreads();
    }

    float s = s_srun[wid];
    float inv = s > 0.f ? 1.f / s : 0.f;
    float x = acc * inv + bias[t * 128 + tid];

    // LayerNorm over 128 dims (block-wide)
    float ws = wsum(x);
    if (lane == 0) s_red[wid] = ws;
    __syncthreads();
    float mean = (s_red[0] + s_red[1] + s_red[2] + s_red[3]) * (1.f / 128.f);
    __syncthreads();
    float d = x - mean;
    float ws2 = wsum(d * d);
    if (lane == 0) s_red[wid] = ws2;
    __syncthreads();
    float var = (s_red[0] + s_red[1] + s_red[2] + s_red[3]) * (1.f / 128.f);
    float rinv = rsqrtf(var + 1e-12f);

    float y = lnw[t * 128 + tid] * (d * rinv) + lnb[t * 128 + tid];
    y = y > 0.f ? y : __expf(y) - 1.f;
    out[(size_t)n * (TT * 128) + t * 128 + tid] = y;
}

// ---------------- launch ----------------
extern "C" void kernel_launch(void* const* d_in, const int* in_sizes, int n_in,
                              void* d_out, int out_size) {
    const float* feature = (const float*)d_in[0];
    const int*   src     = (const int*)d_in[1];
    const int*   dst     = (const int*)d_in[2];
    const float* W       = (const float*)d_in[3];
    const float* al      = (const float*)d_in[4];
    const float* ar      = (const float*)d_in[5];
    const float* bias    = (const float*)d_in[6];
    const float* lnw     = (const float*)d_in[7];
    const float* lnb     = (const float*)d_in[8];
    float* out = (float*)d_out;

    const int smem_gemm = (128 * BS_STRIDE + 128 * AS_STRIDE) * 4;
    static int attr_done = 0;
    if (!attr_done) {
        cudaFuncSetAttribute(gemm_tf32_kernel,
                             cudaFuncAttributeMaxDynamicSharedMemorySize, smem_gemm);
        attr_done = 1;
    }

    init_kernel<<<(TT * NN + 255) / 256, 256>>>();
    gemm_tf32_kernel<<<dim3((NN + 127) / 128, TT), 256, smem_gemm>>>(feature, W);
    elr_kernel<<<dim3((NN + 7) / 8, TT), 256>>>(al, ar);
    hist_kernel<<<dim3((EE + 255) / 256, TT), 256>>>(dst);
    scan_kernel<<<TT, 1024>>>();
    scatter_kernel<<<dim3((EE + 255) / 256, TT), 256>>>(src, dst);
    attn_kernel<<<dim3(NN, TT), 128>>>(bias, lnw, lnb, out);
}

// round 4
// speedup vs baseline: 1.3297x; 1.3297x over previous
#include <cuda_runtime.h>
#include <cuda_fp16.h>
#include <math.h>

#define NN 50000
#define EE 800000
#define TT 2

// ---------------- scratch (static device globals; no allocation) ----------------
__device__ __half  g_fh_h[(size_t)TT * NN * 128];  // projected features (fp16, gather path)
__device__ float4  g_el[TT * NN];                  // per-node left attn logits (4 heads)
__device__ float4  g_er[TT * NN];                  // per-node right attn logits
__device__ int     g_deg[TT * NN];
__device__ int     g_start[TT * NN];
__device__ int     g_cnt[TT * NN];
__device__ int     g_col[TT * EE];                 // CSR-by-dst: src ids

// ---------------- helpers ----------------
__device__ __forceinline__ float lrelu(float x) { return x > 0.f ? x : 0.2f * x; }

__device__ __forceinline__ float wsum(float v) {
#pragma unroll
    for (int o = 16; o > 0; o >>= 1) v += __shfl_xor_sync(0xffffffffu, v, o);
    return v;
}
__device__ __forceinline__ float wmax(float v) {
#pragma unroll
    for (int o = 16; o > 0; o >>= 1) v = fmaxf(v, __shfl_xor_sync(0xffffffffu, v, o));
    return v;
}
__device__ __forceinline__ unsigned tf32u(float x) {
    unsigned u; asm("cvt.rna.tf32.f32 %0, %1;" : "=r"(u) : "f"(x)); return u;
}
__device__ __forceinline__ float tf32f(float x) { return __uint_as_float(tf32u(x)); }

// permute k within each 8-group so (k, k+4) become adjacent: [0,4,1,5,2,6,3,7]
__device__ __forceinline__ int kperm(int k) {
    return (k & ~7) | ((k & 3) << 1) | ((k >> 2) & 1);
}

// ---------------- kernels ----------------
__global__ void init_kernel() {
    int i = blockIdx.x * blockDim.x + threadIdx.x;
    if (i < TT * NN) { g_deg[i] = 0; g_cnt[i] = 0; }
}

// fh[t] = feature @ W[t] via tf32 mma.sync m16n8k8, fp16 output + fused el/er.
// Block 256 thr (8 warps). Tile 128(M) x 128(N), K chunks of 32 (A and B reloaded per chunk).
#define TS 34   // smem k-stride (2-way-max bank conflicts, float2-aligned)
__global__ void __launch_bounds__(256)
gemm_tf32_kernel(const float* __restrict__ feat, const float* __restrict__ W,
                 const float* __restrict__ al, const float* __restrict__ ar) {
    __shared__ float As[128 * TS];
    __shared__ float Bs[128 * TS];

    const int t    = blockIdx.y;
    const int m0   = blockIdx.x * 128;
    const int tid  = threadIdx.x;
    const int lane = tid & 31;
    const int wr   = (tid >> 5) * 16;     // warp row base
    const int q    = lane >> 2;           // 0..7
    const int c2   = (lane & 3) * 2;      // 0,2,4,6

    const float* Wt = W + t * 16384;

    float c[16][4];
#pragma unroll
    for (int j = 0; j < 16; j++)
#pragma unroll
        for (int v = 0; v < 4; v++) c[j][v] = 0.f;

    for (int kt = 0; kt < 128; kt += 32) {
        // A chunk: 128 rows x 32 k
#pragma unroll
        for (int i = 0; i < 4; i++) {
            int qq  = tid + i * 256;
            int row = qq >> 3;
            int kc  = (qq & 7) * 4;
            int gr  = m0 + row;
            float4 v = (gr < NN) ? *(const float4*)(feat + (size_t)gr * 128 + kt + kc)
                                 : make_float4(0.f, 0.f, 0.f, 0.f);
            As[row * TS + kperm(kc + 0)] = tf32f(v.x);
            As[row * TS + kperm(kc + 1)] = tf32f(v.y);
            As[row * TS + kperm(kc + 2)] = tf32f(v.z);
            As[row * TS + kperm(kc + 3)] = tf32f(v.w);
        }
        // B chunk: k in [kt,kt+32), all 128 n; transpose into Bs[n][kperm(klocal)]
#pragma unroll
        for (int i = 0; i < 16; i++) {
            int e  = tid + i * 256;
            int kl = e >> 7;
            int n  = e & 127;
            Bs[n * TS + kperm(kl)] = tf32f(Wt[(size_t)(kt + kl) * 128 + n]);
        }
        __syncthreads();

#pragma unroll
        for (int kk = 0; kk < 32; kk += 8) {
            float2 fa0 = *(const float2*)&As[(wr + q)     * TS + kk + c2];
            float2 fa1 = *(const float2*)&As[(wr + q + 8) * TS + kk + c2];
            unsigned a0 = __float_as_uint(fa0.x), a2 = __float_as_uint(fa0.y);
            unsigned a1 = __float_as_uint(fa1.x), a3 = __float_as_uint(fa1.y);
#pragma unroll
            for (int j = 0; j < 16; j++) {
                float2 fb = *(const float2*)&Bs[(j * 8 + q) * TS + kk + c2];
                unsigned b0 = __float_as_uint(fb.x), b1 = __float_as_uint(fb.y);
                asm volatile(
                    "mma.sync.aligned.m16n8k8.row.col.f32.tf32.tf32.f32 "
                    "{%0,%1,%2,%3},{%4,%5,%6,%7},{%8,%9},{%0,%1,%2,%3};"
                    : "+f"(c[j][0]), "+f"(c[j][1]), "+f"(c[j][2]), "+f"(c[j][3])
                    : "r"(a0), "r"(a1), "r"(a2), "r"(a3), "r"(b0), "r"(b1));
            }
        }
        __syncthreads();
    }

    // ---- epilogue ----
    // lane holds rows r0 = m0+wr+q (c[j][0..1]) and r1 = r0+8 (c[j][2..3]),
    // cols j*8+c2, j*8+c2+1. head(col) = j>>2.
    int r0 = m0 + wr + q;
    int r1 = r0 + 8;
    __half* fhT = g_fh_h + (size_t)t * NN * 128;

    float el0[4], er0[4], el1[4], er1[4];
#pragma unroll
    for (int h = 0; h < 4; h++) { el0[h] = er0[h] = el1[h] = er1[h] = 0.f; }

#pragma unroll
    for (int j = 0; j < 16; j++) {
        int col = j * 8 + c2;
        int h   = j >> 2;
        float2 a2 = *(const float2*)&al[t * 128 + col];
        float2 b2 = *(const float2*)&ar[t * 128 + col];
        el0[h] += c[j][0] * a2.x + c[j][1] * a2.y;
        er0[h] += c[j][0] * b2.x + c[j][1] * b2.y;
        el1[h] += c[j][2] * a2.x + c[j][3] * a2.y;
        er1[h] += c[j][2] * b2.x + c[j][3] * b2.y;
        if (r0 < NN)
            *(__half2*)(fhT + (size_t)r0 * 128 + col) = __floats2half2_rn(c[j][0], c[j][1]);
        if (r1 < NN)
            *(__half2*)(fhT + (size_t)r1 * 128 + col) = __floats2half2_rn(c[j][2], c[j][3]);
    }
    // reduce across the 4 lanes sharing q (lanes q*4 .. q*4+3)
#pragma unroll
    for (int h = 0; h < 4; h++) {
        el0[h] += __shfl_xor_sync(0xffffffffu, el0[h], 1);
        el0[h] += __shfl_xor_sync(0xffffffffu, el0[h], 2);
        er0[h] += __shfl_xor_sync(0xffffffffu, er0[h], 1);
        er0[h] += __shfl_xor_sync(0xffffffffu, er0[h], 2);
        el1[h] += __shfl_xor_sync(0xffffffffu, el1[h], 1);
        el1[h] += __shfl_xor_sync(0xffffffffu, el1[h], 2);
        er1[h] += __shfl_xor_sync(0xffffffffu, er1[h], 1);
        er1[h] += __shfl_xor_sync(0xffffffffu, er1[h], 2);
    }
    if ((lane & 3) == 0) {
        if (r0 < NN) {
            g_el[t * NN + r0] = make_float4(el0[0], el0[1], el0[2], el0[3]);
            g_er[t * NN + r0] = make_float4(er0[0], er0[1], er0[2], er0[3]);
        }
        if (r1 < NN) {
            g_el[t * NN + r1] = make_float4(el1[0], el1[1], el1[2], el1[3]);
            g_er[t * NN + r1] = make_float4(er1[0], er1[1], er1[2], er1[3]);
        }
    }
}

__global__ void hist_kernel(const int* __restrict__ dst) {
    int i = blockIdx.x * blockDim.x + threadIdx.x;
    int t = blockIdx.y;
    if (i < EE) atomicAdd(&g_deg[t * NN + dst[t * EE + i]], 1);
}

// exclusive scan of degrees -> start offsets. One block per type.
__global__ void scan_kernel() {
    __shared__ int sm[1024];
    int t = blockIdx.x;
    const int* deg = &g_deg[t * NN];
    int* st = &g_start[t * NN];
    int tid = threadIdx.x;
    const int C = (NN + 1023) / 1024;
    int base = tid * C;
    int s = 0;
    for (int i = 0; i < C; i++) { int idx = base + i; if (idx < NN) s += deg[idx]; }
    sm[tid] = s;
    __syncthreads();
    for (int off = 1; off < 1024; off <<= 1) {
        int v = (tid >= off) ? sm[tid - off] : 0;
        __syncthreads();
        sm[tid] += v;
        __syncthreads();
    }
    int run = sm[tid] - s;
    for (int i = 0; i < C; i++) {
        int idx = base + i;
        if (idx < NN) { st[idx] = run; run += deg[idx]; }
    }
}

__global__ void scatter_kernel(const int* __restrict__ src, const int* __restrict__ dst) {
    int i = blockIdx.x * blockDim.x + threadIdx.x;
    int t = blockIdx.y;
    if (i >= EE) return;
    int d = dst[t * EE + i];
    int p = g_start[t * NN + d] + atomicAdd(&g_cnt[t * NN + d], 1);
    g_col[t * EE + p] = src[t * EE + i];
}

// fused attention + aggregation + bias + LayerNorm + ELU.
// One WARP per (node, type). Lane l owns dims (2l,2l+1) [head l>>4] and (64+2l,65+2l) [head 2+(l>>4)].
__global__ void __launch_bounds__(256)
attn_kernel(const float* __restrict__ bias, const float* __restrict__ lnw,
            const float* __restrict__ lnb, float* __restrict__ out) {
    __shared__ float4 s_w[8][32];
    __shared__ int    s_c[8][32];

    const float NEG_INF = __int_as_float(0xff800000);
    int tid  = threadIdx.x;
    int lane = tid & 31;
    int w    = tid >> 5;
    int n    = blockIdx.x * 8 + w;
    int t    = blockIdx.y;
    if (n >= NN) return;
    int base = t * NN + n;

    float4 er4 = g_er[base];
    int beg = g_start[base];
    int deg = g_deg[base];
    const int*     colT = g_col + t * EE;
    const float4*  elT  = g_el + t * NN;
    const __half2* fhh  = (const __half2*)(g_fh_h + (size_t)t * NN * 128);

    // ---- pass A: per-head max over incident edges ----
    float m0 = NEG_INF, m1 = NEG_INF, m2 = NEG_INF, m3 = NEG_INF;
    for (int i = beg + lane; i < beg + deg; i += 32) {
        float4 el4 = elT[colT[i]];
        m0 = fmaxf(m0, lrelu(el4.x + er4.x));
        m1 = fmaxf(m1, lrelu(el4.y + er4.y));
        m2 = fmaxf(m2, lrelu(el4.z + er4.z));
        m3 = fmaxf(m3, lrelu(el4.w + er4.w));
    }
    m0 = wmax(m0); m1 = wmax(m1); m2 = wmax(m2); m3 = wmax(m3);

    // ---- pass B: weights + staged coalesced gather ----
    float2 acc0 = make_float2(0.f, 0.f), acc1 = make_float2(0.f, 0.f);
    float s0 = 0.f, s1 = 0.f, s2 = 0.f, s3 = 0.f;
    int hsel = lane >> 4;   // 0 or 1

    for (int pos = 0; pos < deg; pos += 32) {
        int cnt = min(32, deg - pos);
        float4 wv = make_float4(0.f, 0.f, 0.f, 0.f);
        int sc = 0;
        if (lane < cnt) {
            sc = colT[beg + pos + lane];
            float4 el4 = elT[sc];
            wv.x = __expf(lrelu(el4.x + er4.x) - m0);
            wv.y = __expf(lrelu(el4.y + er4.y) - m1);
            wv.z = __expf(lrelu(el4.z + er4.z) - m2);
            wv.w = __expf(lrelu(el4.w + er4.w) - m3);
        }
        s0 += wv.x; s1 += wv.y; s2 += wv.z; s3 += wv.w;
        s_c[w][lane] = sc;
        s_w[w][lane] = wv;
        __syncwarp();

        const float* wf = (const float*)&s_w[w][0];
        int e = 0;
        for (; e + 4 <= cnt; e += 4) {
#pragma unroll
            for (int u = 0; u < 4; u++) {
                int   sq  = s_c[w][e + u];
                float wlo = wf[(e + u) * 4 + hsel];
                float whi = wf[(e + u) * 4 + 2 + hsel];
                float2 f0 = __half22float2(fhh[(size_t)sq * 64 + lane]);
                float2 f1 = __half22float2(fhh[(size_t)sq * 64 + 32 + lane]);
                acc0.x = fmaf(wlo, f0.x, acc0.x);
                acc0.y = fmaf(wlo, f0.y, acc0.y);
                acc1.x = fmaf(whi, f1.x, acc1.x);
                acc1.y = fmaf(whi, f1.y, acc1.y);
            }
        }
        for (; e < cnt; e++) {
            int   sq  = s_c[w][e];
            float wlo = wf[e * 4 + hsel];
            float whi = wf[e * 4 + 2 + hsel];
            float2 f0 = __half22float2(fhh[(size_t)sq * 64 + lane]);
            float2 f1 = __half22float2(fhh[(size_t)sq * 64 + 32 + lane]);
            acc0.x = fmaf(wlo, f0.x, acc0.x);
            acc0.y = fmaf(wlo, f0.y, acc0.y);
            acc1.x = fmaf(whi, f1.x, acc1.x);
            acc1.y = fmaf(whi, f1.y, acc1.y);
        }
        __syncwarp();
    }

    s0 = wsum(s0); s1 = wsum(s1); s2 = wsum(s2); s3 = wsum(s3);
    float slo = hsel ? s1 : s0;
    float shi = hsel ? s3 : s2;
    float ilo = slo > 0.f ? 1.f / slo : 0.f;
    float ihi = shi > 0.f ? 1.f / shi : 0.f;

    float2 b0 = *(const float2*)&bias[t * 128 + 2 * lane];
    float2 b1 = *(const float2*)&bias[t * 128 + 64 + 2 * lane];
    float x0 = acc0.x * ilo + b0.x;
    float x1 = acc0.y * ilo + b0.y;
    float x2 = acc1.x * ihi + b1.x;
    float x3 = acc1.y * ihi + b1.y;

    float mean = wsum(x0 + x1 + x2 + x3) * (1.f / 128.f);
    float d0 = x0 - mean, d1 = x1 - mean, d2 = x2 - mean, d3 = x3 - mean;
    float var = wsum(d0 * d0 + d1 * d1 + d2 * d2 + d3 * d3) * (1.f / 128.f);
    float rinv = rsqrtf(var + 1e-12f);

    float2 w0 = *(const float2*)&lnw[t * 128 + 2 * lane];
    float2 w1 = *(const float2*)&lnw[t * 128 + 64 + 2 * lane];
    float2 c0 = *(const float2*)&lnb[t * 128 + 2 * lane];
    float2 c1 = *(const float2*)&lnb[t * 128 + 64 + 2 * lane];
    float y0 = w0.x * (d0 * rinv) + c0.x;
    float y1 = w0.y * (d1 * rinv) + c0.y;
    float y2 = w1.x * (d2 * rinv) + c1.x;
    float y3 = w1.y * (d3 * rinv) + c1.y;
    y0 = y0 > 0.f ? y0 : __expf(y0) - 1.f;
    y1 = y1 > 0.f ? y1 : __expf(y1) - 1.f;
    y2 = y2 > 0.f ? y2 : __expf(y2) - 1.f;
    y3 = y3 > 0.f ? y3 : __expf(y3) - 1.f;

    float* o = out + (size_t)n * (TT * 128) + t * 128;
    *(float2*)(o + 2 * lane)      = make_float2(y0, y1);
    *(float2*)(o + 64 + 2 * lane) = make_float2(y2, y3);
}

// ---------------- launch ----------------
extern "C" void kernel_launch(void* const* d_in, const int* in_sizes, int n_in,
                              void* d_out, int out_size) {
    const float* feature = (const float*)d_in[0];
    const int*   src     = (const int*)d_in[1];
    const int*   dst     = (const int*)d_in[2];
    const float* W       = (const float*)d_in[3];
    const float* al      = (const float*)d_in[4];
    const float* ar      = (const float*)d_in[5];
    const float* bias    = (const float*)d_in[6];
    const float* lnw     = (const float*)d_in[7];
    const float* lnb     = (const float*)d_in[8];
    float* out = (float*)d_out;

    init_kernel<<<(TT * NN + 255) / 256, 256>>>();
    hist_kernel<<<dim3((EE + 255) / 256, TT), 256>>>(dst);
    gemm_tf32_kernel<<<dim3((NN + 127) / 128, TT), 256>>>(feature, W, al, ar);
    scan_kernel<<<TT, 1024>>>();
    scatter_kernel<<<dim3((EE + 255) / 256, TT), 256>>>(src, dst);
    attn_kernel<<<dim3((NN + 7) / 8, TT), 256>>>(bias, lnw, lnb, out);
}

// round 5
// speedup vs baseline: 1.6970x; 1.2763x over previous
#include <cuda_runtime.h>
#include <cuda_fp16.h>
#include <math.h>

#define NN 50000
#define EE 800000
#define TT 2
#define NB 49   // scan blocks per type: 49*1024 >= NN

// ---------------- scratch (static device globals; no allocation) ----------------
__device__ __half  g_fh_h[(size_t)TT * NN * 128];  // projected features (fp16, gather path)
__device__ float4  g_el[TT * NN];                  // per-node left attn logits (4 heads)
__device__ float4  g_er[TT * NN];                  // per-node right attn logits
__device__ int     g_deg[TT * NN];
__device__ int     g_start[TT * NN];
__device__ int     g_cnt[TT * NN];
__device__ int     g_col[TT * EE];                 // CSR-by-dst: src ids
__device__ int     g_part[TT * NB];                // per-block degree sums
__device__ int     g_partoff[TT * NB];             // exclusive-scanned block offsets

// ---------------- helpers ----------------
__device__ __forceinline__ float lrelu(float x) { return x > 0.f ? x : 0.2f * x; }

__device__ __forceinline__ float wsum(float v) {
#pragma unroll
    for (int o = 16; o > 0; o >>= 1) v += __shfl_xor_sync(0xffffffffu, v, o);
    return v;
}
__device__ __forceinline__ float wmax(float v) {
#pragma unroll
    for (int o = 16; o > 0; o >>= 1) v = fmaxf(v, __shfl_xor_sync(0xffffffffu, v, o));
    return v;
}
__device__ __forceinline__ int wisum(int v) {
#pragma unroll
    for (int o = 16; o > 0; o >>= 1) v += __shfl_xor_sync(0xffffffffu, v, o);
    return v;
}
__device__ __forceinline__ unsigned tf32u(float x) {
    unsigned u; asm("cvt.rna.tf32.f32 %0, %1;" : "=r"(u) : "f"(x)); return u;
}
__device__ __forceinline__ float tf32f(float x) { return __uint_as_float(tf32u(x)); }

// permute k within each 8-group so (k, k+4) become adjacent: [0,4,1,5,2,6,3,7]
__device__ __forceinline__ int kperm(int k) {
    return (k & ~7) | ((k & 3) << 1) | ((k >> 2) & 1);
}

// ---------------- CSR build ----------------
__global__ void init_kernel() {
    int i = blockIdx.x * blockDim.x + threadIdx.x;
    if (i < TT * NN) { g_deg[i] = 0; g_cnt[i] = 0; }
}

__global__ void hist_kernel(const int* __restrict__ dst) {
    int i = blockIdx.x * blockDim.x + threadIdx.x;
    int t = blockIdx.y;
    if (i < EE) atomicAdd(&g_deg[t * NN + dst[t * EE + i]], 1);
}

// stage 1: per-block (1024-elem) degree sums
__global__ void partial_kernel() {
    __shared__ int red[8];
    int t   = blockIdx.y;
    int b   = blockIdx.x;
    int tid = threadIdx.x;           // 256
    int lane = tid & 31, wid = tid >> 5;
    int idx = b * 1024 + tid * 4;
    int s = 0;
    if (idx < NN) {                  // NN % 4 == 0 -> full int4 in range
        int4 v = *(const int4*)&g_deg[t * NN + idx];
        s = v.x + v.y + v.z + v.w;
    }
    s = wisum(s);
    if (lane == 0) red[wid] = s;
    __syncthreads();
    if (tid == 0) {
        int tot = 0;
#pragma unroll
        for (int i = 0; i < 8; i++) tot += red[i];
        g_part[t * NB + b] = tot;
    }
}

// stage 2: exclusive scan of NB partials per type (1 small block)
__global__ void scanpart_kernel() {
    __shared__ int sm[TT][64];
    int tid = threadIdx.x;           // 128
    int ty = tid >> 6, i = tid & 63;
    int v = (i < NB) ? g_part[ty * NB + i] : 0;
    sm[ty][i] = v;
    __syncthreads();
#pragma unroll
    for (int off = 1; off < 64; off <<= 1) {
        int u = (i >= off) ? sm[ty][i - off] : 0;
        __syncthreads();
        sm[ty][i] += u;
        __syncthreads();
    }
    if (i < NB) g_partoff[ty * NB + i] = sm[ty][i] - v;   // exclusive
}

// stage 3: per-block local scan + global offset -> g_start
__global__ void writestart_kernel() {
    __shared__ int wsums[8];
    int t   = blockIdx.y;
    int b   = blockIdx.x;
    int tid = threadIdx.x;           // 256
    int lane = tid & 31, wid = tid >> 5;
    int idx = b * 1024 + tid * 4;

    int d0 = 0, d1 = 0, d2 = 0, d3 = 0;
    if (idx < NN) {
        int4 v = *(const int4*)&g_deg[t * NN + idx];
        d0 = v.x; d1 = v.y; d2 = v.z; d3 = v.w;
    }
    int th = d0 + d1 + d2 + d3;
    // warp inclusive scan
    int incl = th;
#pragma unroll
    for (int off = 1; off < 32; off <<= 1) {
        int u = __shfl_up_sync(0xffffffffu, incl, off);
        if (lane >= off) incl += u;
    }
    int excl = incl - th;
    if (lane == 31) wsums[wid] = incl;
    __syncthreads();
    int woff = 0;
#pragma unroll
    for (int i = 0; i < 8; i++) woff += (i < wid) ? wsums[i] : 0;
    if (idx < NN) {
        int base = g_partoff[t * NB + b] + woff + excl;
        int4 st;
        st.x = base;
        st.y = base + d0;
        st.z = base + d0 + d1;
        st.w = base + d0 + d1 + d2;
        *(int4*)&g_start[t * NN + idx] = st;
    }
}

__global__ void scatter_kernel(const int* __restrict__ src, const int* __restrict__ dst) {
    int i = blockIdx.x * blockDim.x + threadIdx.x;
    int t = blockIdx.y;
    if (i >= EE) return;
    int d = dst[t * EE + i];
    int p = g_start[t * NN + d] + atomicAdd(&g_cnt[t * NN + d], 1);
    g_col[t * EE + p] = src[t * EE + i];
}

// ---------------- GEMM (tf32 mma) + fused el/er, fp16 fh output ----------------
#define TS 34   // smem k-stride
__global__ void __launch_bounds__(256)
gemm_tf32_kernel(const float* __restrict__ feat, const float* __restrict__ W,
                 const float* __restrict__ al, const float* __restrict__ ar) {
    __shared__ float As[128 * TS];
    __shared__ float Bs[128 * TS];

    const int t    = blockIdx.y;
    const int m0   = blockIdx.x * 128;
    const int tid  = threadIdx.x;
    const int lane = tid & 31;
    const int wr   = (tid >> 5) * 16;
    const int q    = lane >> 2;
    const int c2   = (lane & 3) * 2;

    const float* Wt = W + t * 16384;

    float c[16][4];
#pragma unroll
    for (int j = 0; j < 16; j++)
#pragma unroll
        for (int v = 0; v < 4; v++) c[j][v] = 0.f;

    for (int kt = 0; kt < 128; kt += 32) {
#pragma unroll
        for (int i = 0; i < 4; i++) {
            int qq  = tid + i * 256;
            int row = qq >> 3;
            int kc  = (qq & 7) * 4;
            int gr  = m0 + row;
            float4 v = (gr < NN) ? *(const float4*)(feat + (size_t)gr * 128 + kt + kc)
                                 : make_float4(0.f, 0.f, 0.f, 0.f);
            As[row * TS + kperm(kc + 0)] = tf32f(v.x);
            As[row * TS + kperm(kc + 1)] = tf32f(v.y);
            As[row * TS + kperm(kc + 2)] = tf32f(v.z);
            As[row * TS + kperm(kc + 3)] = tf32f(v.w);
        }
#pragma unroll
        for (int i = 0; i < 16; i++) {
            int e  = tid + i * 256;
            int kl = e >> 7;
            int n  = e & 127;
            Bs[n * TS + kperm(kl)] = tf32f(Wt[(size_t)(kt + kl) * 128 + n]);
        }
        __syncthreads();

#pragma unroll
        for (int kk = 0; kk < 32; kk += 8) {
            float2 fa0 = *(const float2*)&As[(wr + q)     * TS + kk + c2];
            float2 fa1 = *(const float2*)&As[(wr + q + 8) * TS + kk + c2];
            unsigned a0 = __float_as_uint(fa0.x), a2 = __float_as_uint(fa0.y);
            unsigned a1 = __float_as_uint(fa1.x), a3 = __float_as_uint(fa1.y);
#pragma unroll
            for (int j = 0; j < 16; j++) {
                float2 fb = *(const float2*)&Bs[(j * 8 + q) * TS + kk + c2];
                unsigned b0 = __float_as_uint(fb.x), b1 = __float_as_uint(fb.y);
                asm volatile(
                    "mma.sync.aligned.m16n8k8.row.col.f32.tf32.tf32.f32 "
                    "{%0,%1,%2,%3},{%4,%5,%6,%7},{%8,%9},{%0,%1,%2,%3};"
                    : "+f"(c[j][0]), "+f"(c[j][1]), "+f"(c[j][2]), "+f"(c[j][3])
                    : "r"(a0), "r"(a1), "r"(a2), "r"(a3), "r"(b0), "r"(b1));
            }
        }
        __syncthreads();
    }

    int r0 = m0 + wr + q;
    int r1 = r0 + 8;
    __half* fhT = g_fh_h + (size_t)t * NN * 128;

    float el0[4], er0[4], el1[4], er1[4];
#pragma unroll
    for (int h = 0; h < 4; h++) { el0[h] = er0[h] = el1[h] = er1[h] = 0.f; }

#pragma unroll
    for (int j = 0; j < 16; j++) {
        int col = j * 8 + c2;
        int h   = j >> 2;
        float2 a2 = *(const float2*)&al[t * 128 + col];
        float2 b2 = *(const float2*)&ar[t * 128 + col];
        el0[h] += c[j][0] * a2.x + c[j][1] * a2.y;
        er0[h] += c[j][0] * b2.x + c[j][1] * b2.y;
        el1[h] += c[j][2] * a2.x + c[j][3] * a2.y;
        er1[h] += c[j][2] * b2.x + c[j][3] * b2.y;
        if (r0 < NN)
            *(__half2*)(fhT + (size_t)r0 * 128 + col) = __floats2half2_rn(c[j][0], c[j][1]);
        if (r1 < NN)
            *(__half2*)(fhT + (size_t)r1 * 128 + col) = __floats2half2_rn(c[j][2], c[j][3]);
    }
#pragma unroll
    for (int h = 0; h < 4; h++) {
        el0[h] += __shfl_xor_sync(0xffffffffu, el0[h], 1);
        el0[h] += __shfl_xor_sync(0xffffffffu, el0[h], 2);
        er0[h] += __shfl_xor_sync(0xffffffffu, er0[h], 1);
        er0[h] += __shfl_xor_sync(0xffffffffu, er0[h], 2);
        el1[h] += __shfl_xor_sync(0xffffffffu, el1[h], 1);
        el1[h] += __shfl_xor_sync(0xffffffffu, el1[h], 2);
        er1[h] += __shfl_xor_sync(0xffffffffu, er1[h], 1);
        er1[h] += __shfl_xor_sync(0xffffffffu, er1[h], 2);
    }
    if ((lane & 3) == 0) {
        if (r0 < NN) {
            g_el[t * NN + r0] = make_float4(el0[0], el0[1], el0[2], el0[3]);
            g_er[t * NN + r0] = make_float4(er0[0], er0[1], er0[2], er0[3]);
        }
        if (r1 < NN) {
            g_el[t * NN + r1] = make_float4(el1[0], el1[1], el1[2], el1[3]);
            g_er[t * NN + r1] = make_float4(er1[0], er1[1], er1[2], er1[3]);
        }
    }
}

// ---------------- fused attention + LayerNorm + ELU ----------------
__global__ void __launch_bounds__(256)
attn_kernel(const float* __restrict__ bias, const float* __restrict__ lnw,
            const float* __restrict__ lnb, float* __restrict__ out) {
    __shared__ float4 s_w[8][32];
    __shared__ int    s_c[8][32];

    const float NEG_INF = __int_as_float(0xff800000);
    int tid  = threadIdx.x;
    int lane = tid & 31;
    int w    = tid >> 5;
    int n    = blockIdx.x * 8 + w;
    int t    = blockIdx.y;
    if (n >= NN) return;
    int base = t * NN + n;

    float4 er4 = g_er[base];
    int beg = g_start[base];
    int deg = g_deg[base];
    const int*     colT = g_col + t * EE;
    const float4*  elT  = g_el + t * NN;
    const __half2* fhh  = (const __half2*)(g_fh_h + (size_t)t * NN * 128);

    float m0 = NEG_INF, m1 = NEG_INF, m2 = NEG_INF, m3 = NEG_INF;
    for (int i = beg + lane; i < beg + deg; i += 32) {
        float4 el4 = elT[colT[i]];
        m0 = fmaxf(m0, lrelu(el4.x + er4.x));
        m1 = fmaxf(m1, lrelu(el4.y + er4.y));
        m2 = fmaxf(m2, lrelu(el4.z + er4.z));
        m3 = fmaxf(m3, lrelu(el4.w + er4.w));
    }
    m0 = wmax(m0); m1 = wmax(m1); m2 = wmax(m2); m3 = wmax(m3);

    float2 acc0 = make_float2(0.f, 0.f), acc1 = make_float2(0.f, 0.f);
    float s0 = 0.f, s1 = 0.f, s2 = 0.f, s3 = 0.f;
    int hsel = lane >> 4;

    for (int pos = 0; pos < deg; pos += 32) {
        int cnt = min(32, deg - pos);
        float4 wv = make_float4(0.f, 0.f, 0.f, 0.f);
        int sc = 0;
        if (lane < cnt) {
            sc = colT[beg + pos + lane];
            float4 el4 = elT[sc];
            wv.x = __expf(lrelu(el4.x + er4.x) - m0);
            wv.y = __expf(lrelu(el4.y + er4.y) - m1);
            wv.z = __expf(lrelu(el4.z + er4.z) - m2);
            wv.w = __expf(lrelu(el4.w + er4.w) - m3);
        }
        s0 += wv.x; s1 += wv.y; s2 += wv.z; s3 += wv.w;
        s_c[w][lane] = sc;
        s_w[w][lane] = wv;
        __syncwarp();

        const float* wf = (const float*)&s_w[w][0];
        int e = 0;
        for (; e + 4 <= cnt; e += 4) {
#pragma unroll
            for (int u = 0; u < 4; u++) {
                int   sq  = s_c[w][e + u];
                float wlo = wf[(e + u) * 4 + hsel];
                float whi = wf[(e + u) * 4 + 2 + hsel];
                float2 f0 = __half22float2(fhh[(size_t)sq * 64 + lane]);
                float2 f1 = __half22float2(fhh[(size_t)sq * 64 + 32 + lane]);
                acc0.x = fmaf(wlo, f0.x, acc0.x);
                acc0.y = fmaf(wlo, f0.y, acc0.y);
                acc1.x = fmaf(whi, f1.x, acc1.x);
                acc1.y = fmaf(whi, f1.y, acc1.y);
            }
        }
        for (; e < cnt; e++) {
            int   sq  = s_c[w][e];
            float wlo = wf[e * 4 + hsel];
            float whi = wf[e * 4 + 2 + hsel];
            float2 f0 = __half22float2(fhh[(size_t)sq * 64 + lane]);
            float2 f1 = __half22float2(fhh[(size_t)sq * 64 + 32 + lane]);
            acc0.x = fmaf(wlo, f0.x, acc0.x);
            acc0.y = fmaf(wlo, f0.y, acc0.y);
            acc1.x = fmaf(whi, f1.x, acc1.x);
            acc1.y = fmaf(whi, f1.y, acc1.y);
        }
        __syncwarp();
    }

    s0 = wsum(s0); s1 = wsum(s1); s2 = wsum(s2); s3 = wsum(s3);
    float slo = hsel ? s1 : s0;
    float shi = hsel ? s3 : s2;
    float ilo = slo > 0.f ? 1.f / slo : 0.f;
    float ihi = shi > 0.f ? 1.f / shi : 0.f;

    float2 b0 = *(const float2*)&bias[t * 128 + 2 * lane];
    float2 b1 = *(const float2*)&bias[t * 128 + 64 + 2 * lane];
    float x0 = acc0.x * ilo + b0.x;
    float x1 = acc0.y * ilo + b0.y;
    float x2 = acc1.x * ihi + b1.x;
    float x3 = acc1.y * ihi + b1.y;

    float mean = wsum(x0 + x1 + x2 + x3) * (1.f / 128.f);
    float d0 = x0 - mean, d1 = x1 - mean, d2 = x2 - mean, d3 = x3 - mean;
    float var = wsum(d0 * d0 + d1 * d1 + d2 * d2 + d3 * d3) * (1.f / 128.f);
    float rinv = rsqrtf(var + 1e-12f);

    float2 w0 = *(const float2*)&lnw[t * 128 + 2 * lane];
    float2 w1 = *(const float2*)&lnw[t * 128 + 64 + 2 * lane];
    float2 c0 = *(const float2*)&lnb[t * 128 + 2 * lane];
    float2 c1 = *(const float2*)&lnb[t * 128 + 64 + 2 * lane];
    float y0 = w0.x * (d0 * rinv) + c0.x;
    float y1 = w0.y * (d1 * rinv) + c0.y;
    float y2 = w1.x * (d2 * rinv) + c1.x;
    float y3 = w1.y * (d3 * rinv) + c1.y;
    y0 = y0 > 0.f ? y0 : __expf(y0) - 1.f;
    y1 = y1 > 0.f ? y1 : __expf(y1) - 1.f;
    y2 = y2 > 0.f ? y2 : __expf(y2) - 1.f;
    y3 = y3 > 0.f ? y3 : __expf(y3) - 1.f;

    float* o = out + (size_t)n * (TT * 128) + t * 128;
    *(float2*)(o + 2 * lane)      = make_float2(y0, y1);
    *(float2*)(o + 64 + 2 * lane) = make_float2(y2, y3);
}

// ---------------- launch ----------------
extern "C" void kernel_launch(void* const* d_in, const int* in_sizes, int n_in,
                              void* d_out, int out_size) {
    const float* feature = (const float*)d_in[0];
    const int*   src     = (const int*)d_in[1];
    const int*   dst     = (const int*)d_in[2];
    const float* W       = (const float*)d_in[3];
    const float* al      = (const float*)d_in[4];
    const float* ar      = (const float*)d_in[5];
    const float* bias    = (const float*)d_in[6];
    const float* lnw     = (const float*)d_in[7];
    const float* lnb     = (const float*)d_in[8];
    float* out = (float*)d_out;

    static cudaStream_t s2 = nullptr;
    static cudaEvent_t ev_fork = nullptr, ev_join = nullptr;
    if (s2 == nullptr) {
        cudaStreamCreateWithFlags(&s2, cudaStreamNonBlocking);
        cudaEventCreateWithFlags(&ev_fork, cudaEventDisableTiming);
        cudaEventCreateWithFlags(&ev_join, cudaEventDisableTiming);
    }

    // fork: CSR build on s2, GEMM on the main (capture) stream
    cudaEventRecord(ev_fork, 0);
    cudaStreamWaitEvent(s2, ev_fork, 0);

    init_kernel<<<(TT * NN + 255) / 256, 256, 0, s2>>>();
    hist_kernel<<<dim3((EE + 255) / 256, TT), 256, 0, s2>>>(dst);
    partial_kernel<<<dim3(NB, TT), 256, 0, s2>>>();
    scanpart_kernel<<<1, 128, 0, s2>>>();
    writestart_kernel<<<dim3(NB, TT), 256, 0, s2>>>();
    scatter_kernel<<<dim3((EE + 255) / 256, TT), 256, 0, s2>>>(src, dst);

    gemm_tf32_kernel<<<dim3((NN + 127) / 128, TT), 256>>>(feature, W, al, ar);

    // join, then fused attention
    cudaEventRecord(ev_join, s2);
    cudaStreamWaitEvent(0, ev_join, 0);
    attn_kernel<<<dim3((NN + 7) / 8, TT), 256>>>(bias, lnw, lnb, out);
}

// round 6
// speedup vs baseline: 1.8596x; 1.0958x over previous
#include <cuda_runtime.h>
#include <cuda_fp16.h>
#include <math.h>

#define NN 50000
#define EE 800000
#define TT 2
#define NB 49   // scan blocks per type: 49*1024 >= NN

// ---------------- scratch (static device globals; no allocation) ----------------
__device__ __half  g_fh_h[(size_t)TT * NN * 128];  // projected features (fp16, gather path)
__device__ float4  g_el[TT * NN];                  // per-node left attn logits (4 heads)
__device__ float4  g_er[TT * NN];                  // per-node right attn logits
__device__ int     g_deg[TT * NN];
__device__ int     g_start[TT * NN];
__device__ int     g_cnt[TT * NN];
__device__ int     g_col[TT * EE];                 // CSR-by-dst: src ids
__device__ int     g_part[TT * NB];
__device__ int     g_partoff[TT * NB];

// ---------------- helpers ----------------
__device__ __forceinline__ float lrelu(float x) { return x > 0.f ? x : 0.2f * x; }

__device__ __forceinline__ float wsum(float v) {
#pragma unroll
    for (int o = 16; o > 0; o >>= 1) v += __shfl_xor_sync(0xffffffffu, v, o);
    return v;
}
__device__ __forceinline__ int wisum(int v) {
#pragma unroll
    for (int o = 16; o > 0; o >>= 1) v += __shfl_xor_sync(0xffffffffu, v, o);
    return v;
}
__device__ __forceinline__ unsigned tf32u(float x) {
    unsigned u; asm("cvt.rna.tf32.f32 %0, %1;" : "=r"(u) : "f"(x)); return u;
}
__device__ __forceinline__ float tf32f(float x) { return __uint_as_float(tf32u(x)); }

// permute k within each 8-group so (k, k+4) become adjacent: [0,4,1,5,2,6,3,7]
__device__ __forceinline__ int kperm(int k) {
    return (k & ~7) | ((k & 3) << 1) | ((k >> 2) & 1);
}

// ---------------- CSR build ----------------
__global__ void init_kernel() {
    int i = blockIdx.x * blockDim.x + threadIdx.x;
    if (i < TT * NN) { g_deg[i] = 0; g_cnt[i] = 0; }
}

__global__ void hist_kernel(const int* __restrict__ dst) {
    int i = blockIdx.x * blockDim.x + threadIdx.x;
    int t = blockIdx.y;
    if (i < EE) atomicAdd(&g_deg[t * NN + dst[t * EE + i]], 1);
}

__global__ void partial_kernel() {
    __shared__ int red[8];
    int t   = blockIdx.y;
    int b   = blockIdx.x;
    int tid = threadIdx.x;           // 256
    int lane = tid & 31, wid = tid >> 5;
    int idx = b * 1024 + tid * 4;
    int s = 0;
    if (idx < NN) {
        int4 v = *(const int4*)&g_deg[t * NN + idx];
        s = v.x + v.y + v.z + v.w;
    }
    s = wisum(s);
    if (lane == 0) red[wid] = s;
    __syncthreads();
    if (tid == 0) {
        int tot = 0;
#pragma unroll
        for (int i = 0; i < 8; i++) tot += red[i];
        g_part[t * NB + b] = tot;
    }
}

__global__ void scanpart_kernel() {
    __shared__ int sm[TT][64];
    int tid = threadIdx.x;           // 128
    int ty = tid >> 6, i = tid & 63;
    int v = (i < NB) ? g_part[ty * NB + i] : 0;
    sm[ty][i] = v;
    __syncthreads();
#pragma unroll
    for (int off = 1; off < 64; off <<= 1) {
        int u = (i >= off) ? sm[ty][i - off] : 0;
        __syncthreads();
        sm[ty][i] += u;
        __syncthreads();
    }
    if (i < NB) g_partoff[ty * NB + i] = sm[ty][i] - v;
}

__global__ void writestart_kernel() {
    __shared__ int wsums[8];
    int t   = blockIdx.y;
    int b   = blockIdx.x;
    int tid = threadIdx.x;           // 256
    int lane = tid & 31, wid = tid >> 5;
    int idx = b * 1024 + tid * 4;

    int d0 = 0, d1 = 0, d2 = 0, d3 = 0;
    if (idx < NN) {
        int4 v = *(const int4*)&g_deg[t * NN + idx];
        d0 = v.x; d1 = v.y; d2 = v.z; d3 = v.w;
    }
    int th = d0 + d1 + d2 + d3;
    int incl = th;
#pragma unroll
    for (int off = 1; off < 32; off <<= 1) {
        int u = __shfl_up_sync(0xffffffffu, incl, off);
        if (lane >= off) incl += u;
    }
    int excl = incl - th;
    if (lane == 31) wsums[wid] = incl;
    __syncthreads();
    int woff = 0;
#pragma unroll
    for (int i = 0; i < 8; i++) woff += (i < wid) ? wsums[i] : 0;
    if (idx < NN) {
        int base = g_partoff[t * NB + b] + woff + excl;
        int4 st;
        st.x = base;
        st.y = base + d0;
        st.z = base + d0 + d1;
        st.w = base + d0 + d1 + d2;
        *(int4*)&g_start[t * NN + idx] = st;
    }
}

__global__ void scatter_kernel(const int* __restrict__ src, const int* __restrict__ dst) {
    int i = blockIdx.x * blockDim.x + threadIdx.x;
    int t = blockIdx.y;
    if (i >= EE) return;
    int d = dst[t * EE + i];
    int p = g_start[t * NN + d] + atomicAdd(&g_cnt[t * NN + d], 1);
    g_col[t * EE + p] = src[t * EE + i];
}

// ---------------- GEMM (tf32 mma) + fused el/er, fp16 fh output ----------------
#define TS 34   // smem k-stride
__global__ void __launch_bounds__(256)
gemm_tf32_kernel(const float* __restrict__ feat, const float* __restrict__ W,
                 const float* __restrict__ al, const float* __restrict__ ar) {
    __shared__ float As[128 * TS];
    __shared__ float Bs[128 * TS];

    const int t    = blockIdx.y;
    const int m0   = blockIdx.x * 128;
    const int tid  = threadIdx.x;
    const int lane = tid & 31;
    const int wr   = (tid >> 5) * 16;
    const int q    = lane >> 2;
    const int c2   = (lane & 3) * 2;

    const float* Wt = W + t * 16384;

    float c[16][4];
#pragma unroll
    for (int j = 0; j < 16; j++)
#pragma unroll
        for (int v = 0; v < 4; v++) c[j][v] = 0.f;

    for (int kt = 0; kt < 128; kt += 32) {
#pragma unroll
        for (int i = 0; i < 4; i++) {
            int qq  = tid + i * 256;
            int row = qq >> 3;
            int kc  = (qq & 7) * 4;
            int gr  = m0 + row;
            float4 v = (gr < NN) ? *(const float4*)(feat + (size_t)gr * 128 + kt + kc)
                                 : make_float4(0.f, 0.f, 0.f, 0.f);
            As[row * TS + kperm(kc + 0)] = tf32f(v.x);
            As[row * TS + kperm(kc + 1)] = tf32f(v.y);
            As[row * TS + kperm(kc + 2)] = tf32f(v.z);
            As[row * TS + kperm(kc + 3)] = tf32f(v.w);
        }
#pragma unroll
        for (int i = 0; i < 16; i++) {
            int e  = tid + i * 256;
            int kl = e >> 7;
            int n  = e & 127;
            Bs[n * TS + kperm(kl)] = tf32f(Wt[(size_t)(kt + kl) * 128 + n]);
        }
        __syncthreads();

#pragma unroll
        for (int kk = 0; kk < 32; kk += 8) {
            float2 fa0 = *(const float2*)&As[(wr + q)     * TS + kk + c2];
            float2 fa1 = *(const float2*)&As[(wr + q + 8) * TS + kk + c2];
            unsigned a0 = __float_as_uint(fa0.x), a2 = __float_as_uint(fa0.y);
            unsigned a1 = __float_as_uint(fa1.x), a3 = __float_as_uint(fa1.y);
#pragma unroll
            for (int j = 0; j < 16; j++) {
                float2 fb = *(const float2*)&Bs[(j * 8 + q) * TS + kk + c2];
                unsigned b0 = __float_as_uint(fb.x), b1 = __float_as_uint(fb.y);
                asm volatile(
                    "mma.sync.aligned.m16n8k8.row.col.f32.tf32.tf32.f32 "
                    "{%0,%1,%2,%3},{%4,%5,%6,%7},{%8,%9},{%0,%1,%2,%3};"
                    : "+f"(c[j][0]), "+f"(c[j][1]), "+f"(c[j][2]), "+f"(c[j][3])
                    : "r"(a0), "r"(a1), "r"(a2), "r"(a3), "r"(b0), "r"(b1));
            }
        }
        __syncthreads();
    }

    int r0 = m0 + wr + q;
    int r1 = r0 + 8;
    __half* fhT = g_fh_h + (size_t)t * NN * 128;

    float el0[4], er0[4], el1[4], er1[4];
#pragma unroll
    for (int h = 0; h < 4; h++) { el0[h] = er0[h] = el1[h] = er1[h] = 0.f; }

#pragma unroll
    for (int j = 0; j < 16; j++) {
        int col = j * 8 + c2;
        int h   = j >> 2;
        float2 a2 = *(const float2*)&al[t * 128 + col];
        float2 b2 = *(const float2*)&ar[t * 128 + col];
        el0[h] += c[j][0] * a2.x + c[j][1] * a2.y;
        er0[h] += c[j][0] * b2.x + c[j][1] * b2.y;
        el1[h] += c[j][2] * a2.x + c[j][3] * a2.y;
        er1[h] += c[j][2] * b2.x + c[j][3] * b2.y;
        if (r0 < NN)
            *(__half2*)(fhT + (size_t)r0 * 128 + col) = __floats2half2_rn(c[j][0], c[j][1]);
        if (r1 < NN)
            *(__half2*)(fhT + (size_t)r1 * 128 + col) = __floats2half2_rn(c[j][2], c[j][3]);
    }
#pragma unroll
    for (int h = 0; h < 4; h++) {
        el0[h] += __shfl_xor_sync(0xffffffffu, el0[h], 1);
        el0[h] += __shfl_xor_sync(0xffffffffu, el0[h], 2);
        er0[h] += __shfl_xor_sync(0xffffffffu, er0[h], 1);
        er0[h] += __shfl_xor_sync(0xffffffffu, er0[h], 2);
        el1[h] += __shfl_xor_sync(0xffffffffu, el1[h], 1);
        el1[h] += __shfl_xor_sync(0xffffffffu, el1[h], 2);
        er1[h] += __shfl_xor_sync(0xffffffffu, er1[h], 1);
        er1[h] += __shfl_xor_sync(0xffffffffu, er1[h], 2);
    }
    if ((lane & 3) == 0) {
        if (r0 < NN) {
            g_el[t * NN + r0] = make_float4(el0[0], el0[1], el0[2], el0[3]);
            g_er[t * NN + r0] = make_float4(er0[0], er0[1], er0[2], er0[3]);
        }
        if (r1 < NN) {
            g_el[t * NN + r1] = make_float4(el1[0], el1[1], el1[2], el1[3]);
            g_er[t * NN + r1] = make_float4(er1[0], er1[1], er1[2], er1[3]);
        }
    }
}

// ---------------- fused attention + LayerNorm + ELU ----------------
// One WARP per (node, type). Lane l owns output dims 4l..4l+3 (head = l>>3).
// Single pass: weights = exp(lrelu(el+er)) (bounded logits -> no max shift needed;
// alpha is scale-invariant so result is identical).
__global__ void __launch_bounds__(256)
attn_kernel(const float* __restrict__ bias, const float* __restrict__ lnw,
            const float* __restrict__ lnb, float* __restrict__ out) {
    __shared__ float4 s_w[8][32];
    __shared__ int    s_c[8][32];

    int tid  = threadIdx.x;
    int lane = tid & 31;
    int w    = tid >> 5;
    int n    = blockIdx.x * 8 + w;
    int t    = blockIdx.y;
    if (n >= NN) return;
    int base = t * NN + n;
    int h    = lane >> 3;            // this lane's head

    float4 er4 = g_er[base];
    int beg = g_start[base];
    int deg = g_deg[base];
    const int*    colT = g_col + t * EE;
    const float4* elT  = g_el + t * NN;
    const uint2*  fh2  = (const uint2*)(g_fh_h + (size_t)t * NN * 128);   // 32 uint2/row

    float a0 = 0.f, a1 = 0.f, a2 = 0.f, a3 = 0.f;      // dims 4l..4l+3
    float s0 = 0.f, s1 = 0.f, s2 = 0.f, s3 = 0.f;      // per-head weight sums

    for (int pos = 0; pos < deg; pos += 32) {
        int cnt = min(32, deg - pos);
        float4 wv = make_float4(0.f, 0.f, 0.f, 0.f);
        int sc = 0;
        if (lane < cnt) {
            sc = colT[beg + pos + lane];
            float4 el4 = elT[sc];
            wv.x = __expf(lrelu(el4.x + er4.x));
            wv.y = __expf(lrelu(el4.y + er4.y));
            wv.z = __expf(lrelu(el4.z + er4.z));
            wv.w = __expf(lrelu(el4.w + er4.w));
        }
        s0 += wv.x; s1 += wv.y; s2 += wv.z; s3 += wv.w;
        s_c[w][lane] = sc;
        s_w[w][lane] = wv;
        __syncwarp();

        const float* wf = (const float*)&s_w[w][0];
        int e = 0;
        for (; e + 4 <= cnt; e += 4) {
#pragma unroll
            for (int u = 0; u < 4; u++) {
                int   sq = s_c[w][e + u];
                float wt = wf[(e + u) * 4 + h];
                uint2 rv = fh2[(size_t)sq * 32 + lane];
                float2 f0 = __half22float2(*(__half2*)&rv.x);
                float2 f1 = __half22float2(*(__half2*)&rv.y);
                a0 = fmaf(wt, f0.x, a0);
                a1 = fmaf(wt, f0.y, a1);
                a2 = fmaf(wt, f1.x, a2);
                a3 = fmaf(wt, f1.y, a3);
            }
        }
        for (; e < cnt; e++) {
            int   sq = s_c[w][e];
            float wt = wf[e * 4 + h];
            uint2 rv = fh2[(size_t)sq * 32 + lane];
            float2 f0 = __half22float2(*(__half2*)&rv.x);
            float2 f1 = __half22float2(*(__half2*)&rv.y);
            a0 = fmaf(wt, f0.x, a0);
            a1 = fmaf(wt, f0.y, a1);
            a2 = fmaf(wt, f1.x, a2);
            a3 = fmaf(wt, f1.y, a3);
        }
        __syncwarp();
    }

    s0 = wsum(s0); s1 = wsum(s1); s2 = wsum(s2); s3 = wsum(s3);
    float sh  = (h < 2) ? ((h & 1) ? s1 : s0) : ((h & 1) ? s3 : s2);
    float inv = sh > 0.f ? 1.f / sh : 0.f;

    float4 b4 = *(const float4*)&bias[t * 128 + 4 * lane];
    float x0 = a0 * inv + b4.x;
    float x1 = a1 * inv + b4.y;
    float x2 = a2 * inv + b4.z;
    float x3 = a3 * inv + b4.w;

    float mean = wsum(x0 + x1 + x2 + x3) * (1.f / 128.f);
    float d0 = x0 - mean, d1 = x1 - mean, d2 = x2 - mean, d3 = x3 - mean;
    float var = wsum(d0 * d0 + d1 * d1 + d2 * d2 + d3 * d3) * (1.f / 128.f);
    float rinv = rsqrtf(var + 1e-12f);

    float4 w4 = *(const float4*)&lnw[t * 128 + 4 * lane];
    float4 c4 = *(const float4*)&lnb[t * 128 + 4 * lane];
    float y0 = w4.x * (d0 * rinv) + c4.x;
    float y1 = w4.y * (d1 * rinv) + c4.y;
    float y2 = w4.z * (d2 * rinv) + c4.z;
    float y3 = w4.w * (d3 * rinv) + c4.w;
    y0 = y0 > 0.f ? y0 : __expf(y0) - 1.f;
    y1 = y1 > 0.f ? y1 : __expf(y1) - 1.f;
    y2 = y2 > 0.f ? y2 : __expf(y2) - 1.f;
    y3 = y3 > 0.f ? y3 : __expf(y3) - 1.f;

    *(float4*)(out + (size_t)n * (TT * 128) + t * 128 + 4 * lane) =
        make_float4(y0, y1, y2, y3);
}

// ---------------- launch ----------------
extern "C" void kernel_launch(void* const* d_in, const int* in_sizes, int n_in,
                              void* d_out, int out_size) {
    const float* feature = (const float*)d_in[0];
    const int*   src     = (const int*)d_in[1];
    const int*   dst     = (const int*)d_in[2];
    const float* W       = (const float*)d_in[3];
    const float* al      = (const float*)d_in[4];
    const float* ar      = (const float*)d_in[5];
    const float* bias    = (const float*)d_in[6];
    const float* lnw     = (const float*)d_in[7];
    const float* lnb     = (const float*)d_in[8];
    float* out = (float*)d_out;

    static cudaStream_t s2 = nullptr;
    static cudaEvent_t ev_fork = nullptr, ev_join = nullptr;
    if (s2 == nullptr) {
        cudaStreamCreateWithFlags(&s2, cudaStreamNonBlocking);
        cudaEventCreateWithFlags(&ev_fork, cudaEventDisableTiming);
        cudaEventCreateWithFlags(&ev_join, cudaEventDisableTiming);
    }

    // fork: CSR build on s2, GEMM on the main (capture) stream
    cudaEventRecord(ev_fork, 0);
    cudaStreamWaitEvent(s2, ev_fork, 0);

    init_kernel<<<(TT * NN + 255) / 256, 256, 0, s2>>>();
    hist_kernel<<<dim3((EE + 255) / 256, TT), 256, 0, s2>>>(dst);
    partial_kernel<<<dim3(NB, TT), 256, 0, s2>>>();
    scanpart_kernel<<<1, 128, 0, s2>>>();
    writestart_kernel<<<dim3(NB, TT), 256, 0, s2>>>();
    scatter_kernel<<<dim3((EE + 255) / 256, TT), 256, 0, s2>>>(src, dst);

    gemm_tf32_kernel<<<dim3((NN + 127) / 128, TT), 256>>>(feature, W, al, ar);

    // join, then fused attention
    cudaEventRecord(ev_join, s2);
    cudaStreamWaitEvent(0, ev_join, 0);
    attn_kernel<<<dim3((NN + 7) / 8, TT), 256>>>(bias, lnw, lnb, out);
}

// round 8
// speedup vs baseline: 2.4568x; 1.3212x over previous
#include <cuda_runtime.h>
#include <cuda_fp16.h>
#include <math.h>

#define NN 50000
#define EE 800000
#define TT 2
#define NB 49   // scan blocks per type: 49*1024 >= NN

// ---------------- scratch (static device globals; no allocation) ----------------
__device__ __half  g_fh_h[(size_t)TT * NN * 128];  // projected features (fp16, gather path)
__device__ float4  g_el[TT * NN];                  // per-node left attn logits (4 heads)
__device__ float4  g_er[TT * NN];                  // per-node right attn logits
__device__ int     g_deg[TT * NN];
__device__ int     g_start[TT * NN];
__device__ int     g_cnt[TT * NN];
__device__ int     g_col[TT * EE];                 // CSR-by-dst: src ids
__device__ int     g_part[TT * NB];
__device__ int     g_partoff[TT * NB];

// ---------------- helpers ----------------
__device__ __forceinline__ float lrelu(float x) { return x > 0.f ? x : 0.2f * x; }

__device__ __forceinline__ float wsum(float v) {
#pragma unroll
    for (int o = 16; o > 0; o >>= 1) v += __shfl_xor_sync(0xffffffffu, v, o);
    return v;
}
__device__ __forceinline__ int wisum(int v) {
#pragma unroll
    for (int o = 16; o > 0; o >>= 1) v += __shfl_xor_sync(0xffffffffu, v, o);
    return v;
}
__device__ __forceinline__ unsigned tf32u(float x) {
    unsigned u; asm("cvt.rna.tf32.f32 %0, %1;" : "=r"(u) : "f"(x)); return u;
}
__device__ __forceinline__ float tf32f(float x) { return __uint_as_float(tf32u(x)); }

// permute k within each 8-group so (k, k+4) become adjacent: [0,4,1,5,2,6,3,7]
__device__ __forceinline__ int kperm(int k) {
    return (k & ~7) | ((k & 3) << 1) | ((k >> 2) & 1);
}

// ---------------- CSR build ----------------
__global__ void init_kernel() {
    int i = blockIdx.x * blockDim.x + threadIdx.x;
    if (i < TT * NN) { g_deg[i] = 0; g_cnt[i] = 0; }
}

__global__ void hist_kernel(const int* __restrict__ dst) {
    int i = blockIdx.x * blockDim.x + threadIdx.x;
    int t = blockIdx.y;
    if (i < EE) atomicAdd(&g_deg[t * NN + dst[t * EE + i]], 1);
}

__global__ void partial_kernel() {
    __shared__ int red[8];
    int t   = blockIdx.y;
    int b   = blockIdx.x;
    int tid = threadIdx.x;           // 256
    int lane = tid & 31, wid = tid >> 5;
    int idx = b * 1024 + tid * 4;
    int s = 0;
    if (idx < NN) {
        int4 v = *(const int4*)&g_deg[t * NN + idx];
        s = v.x + v.y + v.z + v.w;
    }
    s = wisum(s);
    if (lane == 0) red[wid] = s;
    __syncthreads();
    if (tid == 0) {
        int tot = 0;
#pragma unroll
        for (int i = 0; i < 8; i++) tot += red[i];
        g_part[t * NB + b] = tot;
    }
}

__global__ void scanpart_kernel() {
    __shared__ int sm[TT][64];
    int tid = threadIdx.x;           // 128
    int ty = tid >> 6, i = tid & 63;
    int v = (i < NB) ? g_part[ty * NB + i] : 0;
    sm[ty][i] = v;
    __syncthreads();
#pragma unroll
    for (int off = 1; off < 64; off <<= 1) {
        int u = (i >= off) ? sm[ty][i - off] : 0;
        __syncthreads();
        sm[ty][i] += u;
        __syncthreads();
    }
    if (i < NB) g_partoff[ty * NB + i] = sm[ty][i] - v;
}

__global__ void writestart_kernel() {
    __shared__ int wsums[8];
    int t   = blockIdx.y;
    int b   = blockIdx.x;
    int tid = threadIdx.x;           // 256
    int lane = tid & 31, wid = tid >> 5;
    int idx = b * 1024 + tid * 4;

    int d0 = 0, d1 = 0, d2 = 0, d3 = 0;
    if (idx < NN) {
        int4 v = *(const int4*)&g_deg[t * NN + idx];
        d0 = v.x; d1 = v.y; d2 = v.z; d3 = v.w;
    }
    int th = d0 + d1 + d2 + d3;
    int incl = th;
#pragma unroll
    for (int off = 1; off < 32; off <<= 1) {
        int u = __shfl_up_sync(0xffffffffu, incl, off);
        if (lane >= off) incl += u;
    }
    int excl = incl - th;
    if (lane == 31) wsums[wid] = incl;
    __syncthreads();
    int woff = 0;
#pragma unroll
    for (int i = 0; i < 8; i++) woff += (i < wid) ? wsums[i] : 0;
    if (idx < NN) {
        int base = g_partoff[t * NB + b] + woff + excl;
        int4 st;
        st.x = base;
        st.y = base + d0;
        st.z = base + d0 + d1;
        st.w = base + d0 + d1 + d2;
        *(int4*)&g_start[t * NN + idx] = st;
    }
}

__global__ void scatter_kernel(const int* __restrict__ src, const int* __restrict__ dst) {
    int i = blockIdx.x * blockDim.x + threadIdx.x;
    int t = blockIdx.y;
    if (i >= EE) return;
    int d = dst[t * EE + i];
    int p = g_start[t * NN + d] + atomicAdd(&g_cnt[t * NN + d], 1);
    g_col[t * EE + p] = src[t * EE + i];
}

// ---------------- GEMM (tf32 mma) + fused el/er, fp16 fh output ----------------
// B resident in smem k-major [128][136] (loaded once; conflict-free store+read).
// A chunked [128][36] with k-permutation, register-prefetched next chunk.
// B fragment: b0 = B[k=tig][n], b1 = B[k=tig+4][n] with tig = lane&3.
#define BSTR 136
#define ASTR 36
#define GEMM_SMEM ((128 * BSTR + 128 * ASTR) * 4)
__global__ void __launch_bounds__(256)
gemm_tf32_kernel(const float* __restrict__ feat, const float* __restrict__ W,
                 const float* __restrict__ al, const float* __restrict__ ar) {
    extern __shared__ float smdyn[];
    float* Bs = smdyn;                    // [k=128][n + pad=136]
    float* As = smdyn + 128 * BSTR;       // [row=128][kperm + pad=36]

    const int t    = blockIdx.y;
    const int m0   = blockIdx.x * 128;
    const int tid  = threadIdx.x;
    const int lane = tid & 31;
    const int wr   = (tid >> 5) * 16;
    const int q    = lane >> 2;           // groupID: n-offset / A row
    const int tig  = lane & 3;            // thread-in-group: k-offset
    const int c2   = tig * 2;             // permuted-k offset for A

    const float* Wt = W + t * 16384;

    // load full B once: coalesced float4 LDG, conflict-free STS
#pragma unroll
    for (int i = 0; i < 16; i++) {
        int e4 = (tid + i * 256) * 4;     // float4 start element
        int k  = e4 >> 7;
        int n  = e4 & 127;
        float4 v = *(const float4*)(Wt + e4);
        Bs[k * BSTR + n + 0] = tf32f(v.x);
        Bs[k * BSTR + n + 1] = tf32f(v.y);
        Bs[k * BSTR + n + 2] = tf32f(v.z);
        Bs[k * BSTR + n + 3] = tf32f(v.w);
    }

    // load A chunk 0
#pragma unroll
    for (int i = 0; i < 4; i++) {
        int qq  = tid + i * 256;
        int row = qq >> 3;
        int kc  = (qq & 7) * 4;
        int gr  = m0 + row;
        float4 v = (gr < NN) ? *(const float4*)(feat + (size_t)gr * 128 + kc)
                             : make_float4(0.f, 0.f, 0.f, 0.f);
        As[row * ASTR + kperm(kc + 0)] = tf32f(v.x);
        As[row * ASTR + kperm(kc + 1)] = tf32f(v.y);
        As[row * ASTR + kperm(kc + 2)] = tf32f(v.z);
        As[row * ASTR + kperm(kc + 3)] = tf32f(v.w);
    }
    __syncthreads();

    float c[16][4];
#pragma unroll
    for (int j = 0; j < 16; j++)
#pragma unroll
        for (int v = 0; v < 4; v++) c[j][v] = 0.f;

    for (int kt = 0; kt < 128; kt += 32) {
        // prefetch next A chunk into registers (overlaps with MMA below)
        float4 pf[4];
        const bool more = (kt + 32) < 128;
        if (more) {
#pragma unroll
            for (int i = 0; i < 4; i++) {
                int qq  = tid + i * 256;
                int row = qq >> 3;
                int kc  = (qq & 7) * 4;
                int gr  = m0 + row;
                pf[i] = (gr < NN) ? *(const float4*)(feat + (size_t)gr * 128 + kt + 32 + kc)
                                  : make_float4(0.f, 0.f, 0.f, 0.f);
            }
        }

#pragma unroll
        for (int kk = 0; kk < 32; kk += 8) {
            float2 fa0 = *(const float2*)&As[(wr + q)     * ASTR + kk + c2];
            float2 fa1 = *(const float2*)&As[(wr + q + 8) * ASTR + kk + c2];
            unsigned a0 = __float_as_uint(fa0.x), a2 = __float_as_uint(fa0.y);
            unsigned a1 = __float_as_uint(fa1.x), a3 = __float_as_uint(fa1.y);
            const float* b0row = &Bs[(kt + kk + tig)     * BSTR + q];
            const float* b1row = &Bs[(kt + kk + tig + 4) * BSTR + q];
#pragma unroll
            for (int j = 0; j < 16; j++) {
                unsigned b0 = __float_as_uint(b0row[j * 8]);
                unsigned b1 = __float_as_uint(b1row[j * 8]);
                asm volatile(
                    "mma.sync.aligned.m16n8k8.row.col.f32.tf32.tf32.f32 "
                    "{%0,%1,%2,%3},{%4,%5,%6,%7},{%8,%9},{%0,%1,%2,%3};"
                    : "+f"(c[j][0]), "+f"(c[j][1]), "+f"(c[j][2]), "+f"(c[j][3])
                    : "r"(a0), "r"(a1), "r"(a2), "r"(a3), "r"(b0), "r"(b1));
            }
        }
        __syncthreads();
        if (more) {
#pragma unroll
            for (int i = 0; i < 4; i++) {
                int qq  = tid + i * 256;
                int row = qq >> 3;
                int kc  = (qq & 7) * 4;
                As[row * ASTR + kperm(kc + 0)] = tf32f(pf[i].x);
                As[row * ASTR + kperm(kc + 1)] = tf32f(pf[i].y);
                As[row * ASTR + kperm(kc + 2)] = tf32f(pf[i].z);
                As[row * ASTR + kperm(kc + 3)] = tf32f(pf[i].w);
            }
            __syncthreads();
        }
    }

    // epilogue: lane holds rows r0 = m0+wr+q (c[j][0..1]) and r1 = r0+8 (c[j][2..3]),
    // cols j*8 + 2*tig, +1. head(col) = j>>2.
    int r0 = m0 + wr + q;
    int r1 = r0 + 8;
    __half* fhT = g_fh_h + (size_t)t * NN * 128;

    float el0[4], er0[4], el1[4], er1[4];
#pragma unroll
    for (int h = 0; h < 4; h++) { el0[h] = er0[h] = el1[h] = er1[h] = 0.f; }

#pragma unroll
    for (int j = 0; j < 16; j++) {
        int col = j * 8 + c2;
        int h   = j >> 2;
        float2 a2 = *(const float2*)&al[t * 128 + col];
        float2 b2 = *(const float2*)&ar[t * 128 + col];
        el0[h] += c[j][0] * a2.x + c[j][1] * a2.y;
        er0[h] += c[j][0] * b2.x + c[j][1] * b2.y;
        el1[h] += c[j][2] * a2.x + c[j][3] * a2.y;
        er1[h] += c[j][2] * b2.x + c[j][3] * b2.y;
        if (r0 < NN)
            *(__half2*)(fhT + (size_t)r0 * 128 + col) = __floats2half2_rn(c[j][0], c[j][1]);
        if (r1 < NN)
            *(__half2*)(fhT + (size_t)r1 * 128 + col) = __floats2half2_rn(c[j][2], c[j][3]);
    }
#pragma unroll
    for (int h = 0; h < 4; h++) {
        el0[h] += __shfl_xor_sync(0xffffffffu, el0[h], 1);
        el0[h] += __shfl_xor_sync(0xffffffffu, el0[h], 2);
        er0[h] += __shfl_xor_sync(0xffffffffu, er0[h], 1);
        er0[h] += __shfl_xor_sync(0xffffffffu, er0[h], 2);
        el1[h] += __shfl_xor_sync(0xffffffffu, el1[h], 1);
        el1[h] += __shfl_xor_sync(0xffffffffu, el1[h], 2);
        er1[h] += __shfl_xor_sync(0xffffffffu, er1[h], 1);
        er1[h] += __shfl_xor_sync(0xffffffffu, er1[h], 2);
    }
    if (tig == 0) {
        if (r0 < NN) {
            g_el[t * NN + r0] = make_float4(el0[0], el0[1], el0[2], el0[3]);
            g_er[t * NN + r0] = make_float4(er0[0], er0[1], er0[2], er0[3]);
        }
        if (r1 < NN) {
            g_el[t * NN + r1] = make_float4(el1[0], el1[1], el1[2], el1[3]);
            g_er[t * NN + r1] = make_float4(er1[0], er1[1], er1[2], er1[3]);
        }
    }
}

// ---------------- fused attention + LayerNorm + ELU ----------------
// One WARP per (node, type). Lane l owns output dims 4l..4l+3 (head = l>>3).
__global__ void __launch_bounds__(256)
attn_kernel(const float* __restrict__ bias, const float* __restrict__ lnw,
            const float* __restrict__ lnb, float* __restrict__ out) {
    __shared__ float4 s_w[8][32];
    __shared__ int    s_c[8][32];

    int tid  = threadIdx.x;
    int lane = tid & 31;
    int w    = tid >> 5;
    int n    = blockIdx.x * 8 + w;
    int t    = blockIdx.y;
    if (n >= NN) return;
    int base = t * NN + n;
    int h    = lane >> 3;

    float4 er4 = g_er[base];
    int beg = g_start[base];
    int deg = g_deg[base];
    const int*    colT = g_col + t * EE;
    const float4* elT  = g_el + t * NN;
    const uint2*  fh2  = (const uint2*)(g_fh_h + (size_t)t * NN * 128);

    float a0 = 0.f, a1 = 0.f, a2 = 0.f, a3 = 0.f;
    float s0 = 0.f, s1 = 0.f, s2 = 0.f, s3 = 0.f;

    for (int pos = 0; pos < deg; pos += 32) {
        int cnt = min(32, deg - pos);
        float4 wv = make_float4(0.f, 0.f, 0.f, 0.f);
        int sc = 0;
        if (lane < cnt) {
            sc = colT[beg + pos + lane];
            float4 el4 = elT[sc];
            wv.x = __expf(lrelu(el4.x + er4.x));
            wv.y = __expf(lrelu(el4.y + er4.y));
            wv.z = __expf(lrelu(el4.z + er4.z));
            wv.w = __expf(lrelu(el4.w + er4.w));
        }
        s0 += wv.x; s1 += wv.y; s2 += wv.z; s3 += wv.w;
        s_c[w][lane] = sc;
        s_w[w][lane] = wv;
        __syncwarp();

        const float* wf = (const float*)&s_w[w][0];
        int e = 0;
        for (; e + 4 <= cnt; e += 4) {
#pragma unroll
            for (int u = 0; u < 4; u++) {
                int   sq = s_c[w][e + u];
                float wt = wf[(e + u) * 4 + h];
                uint2 rv = fh2[(size_t)sq * 32 + lane];
                float2 f0 = __half22float2(*(__half2*)&rv.x);
                float2 f1 = __half22float2(*(__half2*)&rv.y);
                a0 = fmaf(wt, f0.x, a0);
                a1 = fmaf(wt, f0.y, a1);
                a2 = fmaf(wt, f1.x, a2);
                a3 = fmaf(wt, f1.y, a3);
            }
        }
        for (; e < cnt; e++) {
            int   sq = s_c[w][e];
            float wt = wf[e * 4 + h];
            uint2 rv = fh2[(size_t)sq * 32 + lane];
            float2 f0 = __half22float2(*(__half2*)&rv.x);
            float2 f1 = __half22float2(*(__half2*)&rv.y);
            a0 = fmaf(wt, f0.x, a0);
            a1 = fmaf(wt, f0.y, a1);
            a2 = fmaf(wt, f1.x, a2);
            a3 = fmaf(wt, f1.y, a3);
        }
        __syncwarp();
    }

    s0 = wsum(s0); s1 = wsum(s1); s2 = wsum(s2); s3 = wsum(s3);
    float sh  = (h < 2) ? ((h & 1) ? s1 : s0) : ((h & 1) ? s3 : s2);
    float inv = sh > 0.f ? 1.f / sh : 0.f;

    float4 b4 = *(const float4*)&bias[t * 128 + 4 * lane];
    float x0 = a0 * inv + b4.x;
    float x1 = a1 * inv + b4.y;
    float x2 = a2 * inv + b4.z;
    float x3 = a3 * inv + b4.w;

    float mean = wsum(x0 + x1 + x2 + x3) * (1.f / 128.f);
    float d0 = x0 - mean, d1 = x1 - mean, d2 = x2 - mean, d3 = x3 - mean;
    float var = wsum(d0 * d0 + d1 * d1 + d2 * d2 + d3 * d3) * (1.f / 128.f);
    float rinv = rsqrtf(var + 1e-12f);

    float4 w4 = *(const float4*)&lnw[t * 128 + 4 * lane];
    float4 c4 = *(const float4*)&lnb[t * 128 + 4 * lane];
    float y0 = w4.x * (d0 * rinv) + c4.x;
    float y1 = w4.y * (d1 * rinv) + c4.y;
    float y2 = w4.z * (d2 * rinv) + c4.z;
    float y3 = w4.w * (d3 * rinv) + c4.w;
    y0 = y0 > 0.f ? y0 : __expf(y0) - 1.f;
    y1 = y1 > 0.f ? y1 : __expf(y1) - 1.f;
    y2 = y2 > 0.f ? y2 : __expf(y2) - 1.f;
    y3 = y3 > 0.f ? y3 : __expf(y3) - 1.f;

    *(float4*)(out + (size_t)n * (TT * 128) + t * 128 + 4 * lane) =
        make_float4(y0, y1, y2, y3);
}

// ---------------- launch ----------------
extern "C" void kernel_launch(void* const* d_in, const int* in_sizes, int n_in,
                              void* d_out, int out_size) {
    const float* feature = (const float*)d_in[0];
    const int*   src     = (const int*)d_in[1];
    const int*   dst     = (const int*)d_in[2];
    const float* W       = (const float*)d_in[3];
    const float* al      = (const float*)d_in[4];
    const float* ar      = (const float*)d_in[5];
    const float* bias    = (const float*)d_in[6];
    const float* lnw     = (const float*)d_in[7];
    const float* lnb     = (const float*)d_in[8];
    float* out = (float*)d_out;

    static cudaStream_t s2 = nullptr;
    static cudaEvent_t ev_fork = nullptr, ev_join = nullptr;
    if (s2 == nullptr) {
        cudaStreamCreateWithFlags(&s2, cudaStreamNonBlocking);
        cudaEventCreateWithFlags(&ev_fork, cudaEventDisableTiming);
        cudaEventCreateWithFlags(&ev_join, cudaEventDisableTiming);
        cudaFuncSetAttribute(gemm_tf32_kernel,
                             cudaFuncAttributeMaxDynamicSharedMemorySize, GEMM_SMEM);
    }

    // fork: CSR build on s2, GEMM on the main (capture) stream
    cudaEventRecord(ev_fork, 0);
    cudaStreamWaitEvent(s2, ev_fork, 0);

    init_kernel<<<(TT * NN + 255) / 256, 256, 0, s2>>>();
    hist_kernel<<<dim3((EE + 255) / 256, TT), 256, 0, s2>>>(dst);
    partial_kernel<<<dim3(NB, TT), 256, 0, s2>>>();
    scanpart_kernel<<<1, 128, 0, s2>>>();
    writestart_kernel<<<dim3(NB, TT), 256, 0, s2>>>();
    scatter_kernel<<<dim3((EE + 255) / 256, TT), 256, 0, s2>>>(src, dst);

    gemm_tf32_kernel<<<dim3((NN + 127) / 128, TT), 256, GEMM_SMEM>>>(feature, W, al, ar);

    // join, then fused attention
    cudaEventRecord(ev_join, s2);
    cudaStreamWaitEvent(0, ev_join, 0);
    attn_kernel<<<dim3((NN + 7) / 8, TT), 256>>>(bias, lnw, lnb, out);
}